// round 6
// baseline (speedup 1.0000x reference)
#include <cuda_runtime.h>
#include <cuda_fp16.h>
#include <cstdint>

#define NN 40000
#define EE 640000
#define RRL 8
#define HH 128
#define CC 64
#define NRSEG (NN*RRL)
#define NTILES 313          // ceil(40000/128)

// ---------------- scratch (__device__ globals; no allocation) ----------------
__device__ int   g_cnt2[NRSEG];
__device__ float g_inv[NRSEG];
__device__ int   g_offs[NN];
__device__ int   g_cursor[NN];
__device__ int2  g_edge[EE];            // {.x=(rel<<16)|src, .y=scale bits}, dst-grouped
__device__ int   g_bsum[40];
__device__ int   g_bflag[40];
__device__ uint32_t g_w2t[9 * CC * HH];               // W2^T / root2^T tf32 bits [m][c][k]
__device__ __half g_hall[(size_t)RRL * NN * CC];      // h @ W2[r] in fp16, 41 MB (L2-resident)

__device__ __forceinline__ uint32_t f2tf(float x) {
    uint32_t r; asm("cvt.rna.tf32.f32 %0, %1;" : "=r"(r) : "f"(x)); return r;
}

// ---------------- fused: zero counters + transpose W2/root2 to tf32 [m][c][k] ----------------
__global__ void k_fused0(const float* __restrict__ W2, const float* __restrict__ root2) {
    int i = blockIdx.x * blockDim.x + threadIdx.x;
    int stride = gridDim.x * blockDim.x;
    for (int j = i; j < NRSEG; j += stride) {
        g_cnt2[j] = 0;
        if (j < NN) g_cursor[j] = 0;
        if (j < 40) g_bflag[j] = 0;
    }
    for (int j = i; j < 9 * CC * HH; j += stride) {
        int m = j >> 13;
        int rem = j & 8191;
        int c = rem >> 7;
        int k = rem & 127;
        float v = (m < 8) ? W2[((size_t)m * HH + k) * CC + c] : root2[(size_t)k * CC + c];
        g_w2t[j] = f2tf(v);
    }
}

__global__ void k_hist(const int* __restrict__ ei, const int* __restrict__ et) {
    int e = (blockIdx.x * blockDim.x + threadIdx.x) * 2;
    if (e >= EE) return;
    int2 d = *(const int2*)&ei[EE + e];
    int2 r = *(const int2*)&et[e];
    atomicAdd(&g_cnt2[d.x * RRL + r.x], 1);
    atomicAdd(&g_cnt2[d.y * RRL + r.y], 1);
}

// ---------------- single-kernel scan (decoupled lookback) + inv ----------------
__global__ void k_scan() {
    __shared__ int s[1024];
    __shared__ int sprev;
    int b = blockIdx.x, tid = threadIdx.x;
    int i = b * 1024 + tid;
    int v = 0;
    if (i < NN) {
        int4 c0 = ((const int4*)g_cnt2)[i * 2];
        int4 c1 = ((const int4*)g_cnt2)[i * 2 + 1];
        v = c0.x + c0.y + c0.z + c0.w + c1.x + c1.y + c1.z + c1.w;
    }
    s[tid] = v;
    __syncthreads();
    for (int off = 1; off < 1024; off <<= 1) {
        int t = (tid >= off) ? s[tid - off] : 0;
        __syncthreads();
        s[tid] += t;
        __syncthreads();
    }
    if (tid == 1023) {
        int total = s[1023];
        int prev = 0;
        if (b > 0) {
            while (atomicAdd(&g_bflag[b - 1], 0) == 0) { }
            prev = g_bsum[b - 1];
        }
        g_bsum[b] = prev + total;
        __threadfence();
        atomicExch(&g_bflag[b], 1);
        sprev = prev;
    }
    for (int j = b * 1024 + tid; j < NRSEG; j += 40 * 1024) {
        int c = g_cnt2[j];
        g_inv[j] = 1.0f / (float)(c > 0 ? c : 1);
    }
    __syncthreads();
    if (i < NN) g_offs[i] = s[tid] - v + sprev;
}

__global__ void k_perm(const int* __restrict__ ei, const int* __restrict__ et) {
    int e = (blockIdx.x * blockDim.x + threadIdx.x) * 2;
    if (e >= EE) return;
    int2 src = *(const int2*)&ei[e];
    int2 dst = *(const int2*)&ei[EE + e];
    int2 rel = *(const int2*)&et[e];
    int pos0 = g_offs[dst.x] + atomicAdd(&g_cursor[dst.x], 1);
    g_edge[pos0] = make_int2((rel.x << 16) | src.x, __float_as_int(g_inv[dst.x * RRL + rel.x]));
    int pos1 = g_offs[dst.y] + atomicAdd(&g_cursor[dst.y], 1);
    g_edge[pos1] = make_int2((rel.y << 16) | src.y, __float_as_int(g_inv[dst.y * RRL + rel.y]));
}

// ---------------- fused layer1 + GEMM ----------------
// Phase 1: 16 warps x 8 dst rows each -> h tile (relu, tf32 bits) directly in smem As.
// Phase 2: loop r=0..8; stage Bs; tf32 mma; epilogue to g_hall (fp16) / out (fp32).
#define PAD 132
#define SM_TOTAL ((128 + 64) * PAD * 4)   // 101376 bytes

__global__ void __launch_bounds__(512, 2) k_l1gemm(
        const float* __restrict__ W1, const float* __restrict__ root1,
        const float* __restrict__ b1, const float* __restrict__ b2,
        float* __restrict__ out) {
    extern __shared__ uint32_t sm32[];
    uint32_t* As = sm32;               // [128][PAD] tf32 bits
    uint32_t* Bs = sm32 + 128 * PAD;   // [64][PAD]  tf32 bits (B^T: [c][k])
    int t = threadIdx.x;
    int warp = t >> 5, lane = t & 31;
    int tile = blockIdx.x;

    // ---- phase 1: gather 8 dst rows per warp ----
    const float4* W1v = (const float4*)W1;
    float4 bb = ((const float4*)b1)[lane];
    for (int j = 0; j < 8; j++) {
        int row = warp * 8 + j;
        int n = tile * 128 + row;
        if (n >= NN) break;
        int beg = g_offs[n];
        int end = (n == NN - 1) ? EE : g_offs[n + 1];
        int cnt = end - beg;
        float4 acc = ((const float4*)root1)[n * 32 + lane];
        acc.x += bb.x; acc.y += bb.y; acc.z += bb.z; acc.w += bb.w;
        int i = 0;
        for (; i + 8 <= cnt; i += 8) {
            int2 e[8]; float4 v[8];
#pragma unroll
            for (int q = 0; q < 8; q++) e[q] = g_edge[beg + i + q];
#pragma unroll
            for (int q = 0; q < 8; q++)
                v[q] = W1v[(size_t)((e[q].x >> 16) * NN + (e[q].x & 0xFFFF)) * 32 + lane];
#pragma unroll
            for (int q = 0; q < 8; q++) {
                float s = __int_as_float(e[q].y);
                acc.x += v[q].x * s;
                acc.y += v[q].y * s;
                acc.z += v[q].z * s;
                acc.w += v[q].w * s;
            }
        }
        for (; i < cnt; i++) {
            int2 e = g_edge[beg + i];
            float s = __int_as_float(e.y);
            float4 v = W1v[(size_t)((e.x >> 16) * NN + (e.x & 0xFFFF)) * 32 + lane];
            acc.x += v.x * s; acc.y += v.y * s; acc.z += v.z * s; acc.w += v.w * s;
        }
        *(uint4*)&As[row * PAD + lane * 4] = make_uint4(
            f2tf(fmaxf(acc.x, 0.0f)), f2tf(fmaxf(acc.y, 0.0f)),
            f2tf(fmaxf(acc.z, 0.0f)), f2tf(fmaxf(acc.w, 0.0f)));
    }
    __syncthreads();

    // ---- phase 2: 9 r-slices ----
    int g = lane >> 2;        // 0..7
    int kq = lane & 3;        // 0..3
    int wm = warp >> 1;       // 0..7  (m16 group)
    int wn = warp & 1;        // 0..1  (n32 group)
    int rA = wm * 16 + g;
    int n0 = tile * 128 + rA;
    int n1 = n0 + 8;

    for (int r = 0; r < 9; r++) {
        const uint4* bsrc = (const uint4*)(g_w2t + (size_t)r * CC * HH);
#pragma unroll
        for (int jj = 0; jj < 4; jj++) {
            int f = t + jj * 512;          // 0..2047 uint4s
            int row = f >> 5, q = f & 31;
            *(uint4*)&Bs[row * PAD + (q << 2)] = bsrc[f];
        }
        __syncthreads();

        float acc[4][4];
#pragma unroll
        for (int nt = 0; nt < 4; nt++)
#pragma unroll
            for (int q = 0; q < 4; q++) acc[nt][q] = 0.0f;

#pragma unroll
        for (int ks = 0; ks < 16; ks++) {
            int k0 = ks * 8;
            uint32_t a0 = As[rA * PAD + k0 + kq];
            uint32_t a1 = As[(rA + 8) * PAD + k0 + kq];
            uint32_t a2 = As[rA * PAD + k0 + 4 + kq];
            uint32_t a3 = As[(rA + 8) * PAD + k0 + 4 + kq];
#pragma unroll
            for (int nt = 0; nt < 4; nt++) {
                int brow = wn * 32 + nt * 8 + g;
                uint32_t b0 = Bs[brow * PAD + k0 + kq];
                uint32_t b1_ = Bs[brow * PAD + k0 + 4 + kq];
                asm volatile(
                    "mma.sync.aligned.m16n8k8.row.col.f32.tf32.tf32.f32 "
                    "{%0,%1,%2,%3}, {%4,%5,%6,%7}, {%8,%9}, {%0,%1,%2,%3};"
                    : "+f"(acc[nt][0]), "+f"(acc[nt][1]), "+f"(acc[nt][2]), "+f"(acc[nt][3])
                    : "r"(a0), "r"(a1), "r"(a2), "r"(a3), "r"(b0), "r"(b1_));
            }
        }

        if (r < 8) {
            __half* base = g_hall + (size_t)r * NN * CC;
#pragma unroll
            for (int nt = 0; nt < 4; nt++) {
                int c = wn * 32 + nt * 8 + kq * 2;
                if (n0 < NN) *(__half2*)&base[(size_t)n0 * CC + c] = __floats2half2_rn(acc[nt][0], acc[nt][1]);
                if (n1 < NN) *(__half2*)&base[(size_t)n1 * CC + c] = __floats2half2_rn(acc[nt][2], acc[nt][3]);
            }
        } else {
#pragma unroll
            for (int nt = 0; nt < 4; nt++) {
                int c = wn * 32 + nt * 8 + kq * 2;
                float2 bbv = *(const float2*)&b2[c];
                if (n0 < NN) *(float2*)&out[(size_t)n0 * CC + c] = make_float2(acc[nt][0] + bbv.x, acc[nt][1] + bbv.y);
                if (n1 < NN) *(float2*)&out[(size_t)n1 * CC + c] = make_float2(acc[nt][2] + bbv.x, acc[nt][3] + bbv.y);
            }
        }
        __syncthreads();   // Bs reuse safety
    }
}

// ---------------- layer 2: warp per dst, gather fp16 h_all (L2-resident) ----------------
__global__ void k_layer2(float* __restrict__ out) {
    int w = (blockIdx.x * blockDim.x + threadIdx.x) >> 5;
    int lane = threadIdx.x & 31;
    if (w >= NN) return;
    int beg = g_offs[w];
    int end = (w == NN - 1) ? EE : g_offs[w + 1];
    int cnt = end - beg;
    float2 acc = ((float2*)out)[w * 32 + lane];   // h@root2 + b2 from k_l1gemm
    const __half2* hv = (const __half2*)g_hall;
    int i = 0;
    for (; i + 8 <= cnt; i += 8) {
        int2 e[8]; __half2 v[8];
#pragma unroll
        for (int j = 0; j < 8; j++) e[j] = g_edge[beg + i + j];
#pragma unroll
        for (int j = 0; j < 8; j++)
            v[j] = hv[(size_t)((e[j].x >> 16) * NN + (e[j].x & 0xFFFF)) * 32 + lane];
#pragma unroll
        for (int j = 0; j < 8; j++) {
            float s = __int_as_float(e[j].y);
            float2 f = __half22float2(v[j]);
            acc.x += f.x * s;
            acc.y += f.y * s;
        }
    }
    for (; i < cnt; i++) {
        int2 e = g_edge[beg + i];
        float s = __int_as_float(e.y);
        float2 f = __half22float2(hv[(size_t)((e.x >> 16) * NN + (e.x & 0xFFFF)) * 32 + lane]);
        acc.x += f.x * s; acc.y += f.y * s;
    }
    ((float2*)out)[w * 32 + lane] = acc;
}

// ---------------- launch ----------------
extern "C" void kernel_launch(void* const* d_in, const int* in_sizes, int n_in,
                              void* d_out, int out_size) {
    (void)in_sizes; (void)n_in; (void)out_size;
    const int*   ei    = (const int*)d_in[0];
    const int*   et    = (const int*)d_in[1];
    const float* W1    = (const float*)d_in[2];
    const float* root1 = (const float*)d_in[3];
    const float* b1    = (const float*)d_in[4];
    const float* W2    = (const float*)d_in[5];
    const float* root2 = (const float*)d_in[6];
    const float* b2    = (const float*)d_in[7];
    float* out = (float*)d_out;

    k_fused0<<<592, 256>>>(W2, root2);
    k_hist<<<(EE / 2 + 255) / 256, 256>>>(ei, et);
    k_scan<<<40, 1024>>>();
    k_perm<<<(EE / 2 + 255) / 256, 256>>>(ei, et);
    cudaFuncSetAttribute(k_l1gemm, cudaFuncAttributeMaxDynamicSharedMemorySize, SM_TOTAL);
    k_l1gemm<<<NTILES, 512, SM_TOTAL>>>(W1, root1, b1, b2, out);
    k_layer2<<<NN / 8, 256>>>(out);
}

// round 7
// speedup vs baseline: 1.3752x; 1.3752x over previous
#include <cuda_runtime.h>
#include <cuda_fp16.h>
#include <cstdint>

#define NN 40000
#define EE 640000
#define RRL 8
#define HH 128
#define CC 64
#define NRSEG (NN*RRL)
#define NTILES 313          // ceil(40000/128)

// ---------------- scratch (__device__ globals; no allocation) ----------------
__device__ int   g_cnt2[NRSEG];
__device__ float g_inv[NRSEG];
__device__ int   g_offs[NN];
__device__ int   g_cursor[NN];
__device__ int2  g_edge[EE];            // {.x=(rel<<16)|src, .y=scale bits}, dst-grouped
__device__ int   g_bsum[40];
__device__ int   g_bflag[40];
__device__ uint32_t g_h[(size_t)NTILES * 128 * 64];   // layer-1 out, half2-packed [row][64]
__device__ __half g_w2t[9 * CC * HH];                 // W2^T / root2^T fp16 [m][c][k]
__device__ __half g_hall[(size_t)RRL * NN * CC];      // h @ W2[r] in fp16, 41 MB (L2-resident)

// ---------------- fused: zero counters + transpose W2/root2 to fp16 [m][c][k] ----------------
__global__ void k_fused0(const float* __restrict__ W2, const float* __restrict__ root2) {
    int i = blockIdx.x * blockDim.x + threadIdx.x;
    int stride = gridDim.x * blockDim.x;
    for (int j = i; j < NRSEG; j += stride) {
        g_cnt2[j] = 0;
        if (j < NN) g_cursor[j] = 0;
        if (j < 40) g_bflag[j] = 0;
    }
    for (int j = i; j < 9 * CC * HH; j += stride) {
        int m = j >> 13;
        int rem = j & 8191;
        int c = rem >> 7;
        int k = rem & 127;
        float v = (m < 8) ? W2[((size_t)m * HH + k) * CC + c] : root2[(size_t)k * CC + c];
        g_w2t[j] = __float2half_rn(v);
    }
}

__global__ void k_hist(const int* __restrict__ ei, const int* __restrict__ et) {
    int e = blockIdx.x * blockDim.x + threadIdx.x;
    if (e >= EE) return;
    int dst = ei[EE + e];
    int rel = et[e];
    atomicAdd(&g_cnt2[dst * RRL + rel], 1);
}

// ---------------- single-kernel scan (decoupled lookback) + inv ----------------
__global__ void k_scan() {
    __shared__ int s[1024];
    __shared__ int sprev;
    int b = blockIdx.x, tid = threadIdx.x;
    int i = b * 1024 + tid;
    int v = 0;
    if (i < NN) {
        int4 c0 = ((const int4*)g_cnt2)[i * 2];
        int4 c1 = ((const int4*)g_cnt2)[i * 2 + 1];
        v = c0.x + c0.y + c0.z + c0.w + c1.x + c1.y + c1.z + c1.w;
    }
    s[tid] = v;
    __syncthreads();
    for (int off = 1; off < 1024; off <<= 1) {
        int t = (tid >= off) ? s[tid - off] : 0;
        __syncthreads();
        s[tid] += t;
        __syncthreads();
    }
    if (tid == 1023) {
        int total = s[1023];
        int prev = 0;
        if (b > 0) {
            while (atomicAdd(&g_bflag[b - 1], 0) == 0) { }
            prev = g_bsum[b - 1];
        }
        g_bsum[b] = prev + total;
        __threadfence();
        atomicExch(&g_bflag[b], 1);
        sprev = prev;
    }
    for (int j = b * 1024 + tid; j < NRSEG; j += 40 * 1024) {
        int c = g_cnt2[j];
        g_inv[j] = 1.0f / (float)(c > 0 ? c : 1);
    }
    __syncthreads();
    if (i < NN) g_offs[i] = s[tid] - v + sprev;
}

__global__ void k_perm(const int* __restrict__ ei, const int* __restrict__ et) {
    int e = blockIdx.x * blockDim.x + threadIdx.x;
    if (e >= EE) return;
    int dst = ei[EE + e];
    int rel = et[e];
    int src = ei[e];
    int pos = g_offs[dst] + atomicAdd(&g_cursor[dst], 1);
    float s = g_inv[dst * RRL + rel];
    g_edge[pos] = make_int2((rel << 16) | src, __float_as_int(s));
}

// ---------------- layer 1: warp per dst, 8-deep MLP, writes fp16 (half2-packed) ----------------
__global__ void k_layer1(const float* __restrict__ W1, const float* __restrict__ root1,
                         const float* __restrict__ b1) {
    int w = (blockIdx.x * blockDim.x + threadIdx.x) >> 5;
    int lane = threadIdx.x & 31;
    if (w >= NN) return;
    int beg = g_offs[w];
    int end = (w == NN - 1) ? EE : g_offs[w + 1];
    int cnt = end - beg;
    float4 acc = ((const float4*)root1)[w * 32 + lane];
    float4 bb = ((const float4*)b1)[lane];
    acc.x += bb.x; acc.y += bb.y; acc.z += bb.z; acc.w += bb.w;
    const float4* W1v = (const float4*)W1;
    int i = 0;
    for (; i + 8 <= cnt; i += 8) {
        int2 e[8]; float4 v[8];
#pragma unroll
        for (int j = 0; j < 8; j++) e[j] = g_edge[beg + i + j];
#pragma unroll
        for (int j = 0; j < 8; j++)
            v[j] = W1v[(size_t)((e[j].x >> 16) * NN + (e[j].x & 0xFFFF)) * 32 + lane];
#pragma unroll
        for (int j = 0; j < 8; j++) {
            float s = __int_as_float(e[j].y);
            acc.x += v[j].x * s;
            acc.y += v[j].y * s;
            acc.z += v[j].z * s;
            acc.w += v[j].w * s;
        }
    }
    for (; i < cnt; i++) {
        int2 e = g_edge[beg + i];
        float s = __int_as_float(e.y);
        float4 v = W1v[(size_t)((e.x >> 16) * NN + (e.x & 0xFFFF)) * 32 + lane];
        acc.x += v.x * s; acc.y += v.y * s; acc.z += v.z * s; acc.w += v.w * s;
    }
    __half2 p0 = __floats2half2_rn(fmaxf(acc.x, 0.0f), fmaxf(acc.y, 0.0f));
    __half2 p1 = __floats2half2_rn(fmaxf(acc.z, 0.0f), fmaxf(acc.w, 0.0f));
    ((uint2*)g_h)[w * 32 + lane] = make_uint2(*(uint32_t*)&p0, *(uint32_t*)&p1);
}

// ---------------- GEMM via fp16 mma.sync m16n8k16: A staged once, 3 r-slices per CTA ----------------
#define PAD2 68
#define SM_TOTAL ((128 + 64) * PAD2 * 4)   // 52224 bytes

__global__ void __launch_bounds__(256) k_gemm(const float* __restrict__ b2,
                                              float* __restrict__ out) {
    extern __shared__ uint32_t sm32[];
    uint32_t* As = sm32;                // [128][PAD2] half2 words
    uint32_t* Bs = sm32 + 128 * PAD2;   // [64][PAD2]  half2 words (B^T: [c][k])
    int t = threadIdx.x;
    int tile = blockIdx.x;
    int rbase = blockIdx.y * 3;

    // stage A once: 128 rows x 64 half2 words = 2048 uint4
    const uint4* asrc = (const uint4*)(g_h + (size_t)tile * 128 * 64);
#pragma unroll
    for (int j = 0; j < 8; j++) {
        int f = t + j * 256;           // 0..2047
        int row = f >> 4, q = f & 15;
        *(uint4*)&As[row * PAD2 + (q << 2)] = asrc[f];
    }

    int warp = t >> 5, lane = t & 31;
    int g = lane >> 2;        // groupID 0..7
    int tig = lane & 3;       // threadID_in_group
    int rA = warp * 16 + g;
    int n0 = tile * 128 + warp * 16 + g;
    int n1 = n0 + 8;

    for (int rr = 0; rr < 3; rr++) {
        int r = rbase + rr;
        __syncthreads();      // Bs overwrite safety + first-iter As visibility
        // stage B: 64 rows x 64 half2 words = 1024 uint4
        const uint4* bsrc = (const uint4*)(g_w2t + (size_t)r * CC * HH);
#pragma unroll
        for (int j = 0; j < 4; j++) {
            int f = t + j * 256;       // 0..1023
            int row = f >> 4, q = f & 15;
            *(uint4*)&Bs[row * PAD2 + (q << 2)] = bsrc[f];
        }
        __syncthreads();

        float acc[8][4];
#pragma unroll
        for (int nt = 0; nt < 8; nt++)
#pragma unroll
            for (int q = 0; q < 4; q++) acc[nt][q] = 0.0f;

#pragma unroll
        for (int ks = 0; ks < 8; ks++) {
            int j0 = ks * 8 + tig;     // half2-word index; k = 2*j0
            uint32_t a0 = As[rA * PAD2 + j0];
            uint32_t a1 = As[(rA + 8) * PAD2 + j0];
            uint32_t a2 = As[rA * PAD2 + j0 + 4];
            uint32_t a3 = As[(rA + 8) * PAD2 + j0 + 4];
#pragma unroll
            for (int nt = 0; nt < 8; nt++) {
                int brow = nt * 8 + g;
                uint32_t b0 = Bs[brow * PAD2 + j0];
                uint32_t b1_ = Bs[brow * PAD2 + j0 + 4];
                asm volatile(
                    "mma.sync.aligned.m16n8k16.row.col.f32.f16.f16.f32 "
                    "{%0,%1,%2,%3}, {%4,%5,%6,%7}, {%8,%9}, {%0,%1,%2,%3};"
                    : "+f"(acc[nt][0]), "+f"(acc[nt][1]), "+f"(acc[nt][2]), "+f"(acc[nt][3])
                    : "r"(a0), "r"(a1), "r"(a2), "r"(a3), "r"(b0), "r"(b1_));
            }
        }

        if (r < 8) {
            __half* base = g_hall + (size_t)r * NN * CC;
#pragma unroll
            for (int nt = 0; nt < 8; nt++) {
                int c = nt * 8 + tig * 2;
                if (n0 < NN) *(__half2*)&base[(size_t)n0 * CC + c] = __floats2half2_rn(acc[nt][0], acc[nt][1]);
                if (n1 < NN) *(__half2*)&base[(size_t)n1 * CC + c] = __floats2half2_rn(acc[nt][2], acc[nt][3]);
            }
        } else {
#pragma unroll
            for (int nt = 0; nt < 8; nt++) {
                int c = nt * 8 + tig * 2;
                float2 bb = *(const float2*)&b2[c];
                if (n0 < NN) *(float2*)&out[(size_t)n0 * CC + c] = make_float2(acc[nt][0] + bb.x, acc[nt][1] + bb.y);
                if (n1 < NN) *(float2*)&out[(size_t)n1 * CC + c] = make_float2(acc[nt][2] + bb.x, acc[nt][3] + bb.y);
            }
        }
    }
}

// ---------------- layer 2: warp per dst, gather fp16 h_all (L2-resident) ----------------
__global__ void k_layer2(float* __restrict__ out) {
    int w = (blockIdx.x * blockDim.x + threadIdx.x) >> 5;
    int lane = threadIdx.x & 31;
    if (w >= NN) return;
    int beg = g_offs[w];
    int end = (w == NN - 1) ? EE : g_offs[w + 1];
    int cnt = end - beg;
    float2 acc = ((float2*)out)[w * 32 + lane];   // h@root2 + b2 from k_gemm
    const __half2* hv = (const __half2*)g_hall;
    int i = 0;
    for (; i + 8 <= cnt; i += 8) {
        int2 e[8]; __half2 v[8];
#pragma unroll
        for (int j = 0; j < 8; j++) e[j] = g_edge[beg + i + j];
#pragma unroll
        for (int j = 0; j < 8; j++)
            v[j] = hv[(size_t)((e[j].x >> 16) * NN + (e[j].x & 0xFFFF)) * 32 + lane];
#pragma unroll
        for (int j = 0; j < 8; j++) {
            float s = __int_as_float(e[j].y);
            float2 f = __half22float2(v[j]);
            acc.x += f.x * s;
            acc.y += f.y * s;
        }
    }
    for (; i < cnt; i++) {
        int2 e = g_edge[beg + i];
        float s = __int_as_float(e.y);
        float2 f = __half22float2(hv[(size_t)((e.x >> 16) * NN + (e.x & 0xFFFF)) * 32 + lane]);
        acc.x += f.x * s; acc.y += f.y * s;
    }
    ((float2*)out)[w * 32 + lane] = acc;
}

// ---------------- launch ----------------
extern "C" void kernel_launch(void* const* d_in, const int* in_sizes, int n_in,
                              void* d_out, int out_size) {
    (void)in_sizes; (void)n_in; (void)out_size;
    const int*   ei    = (const int*)d_in[0];
    const int*   et    = (const int*)d_in[1];
    const float* W1    = (const float*)d_in[2];
    const float* root1 = (const float*)d_in[3];
    const float* b1    = (const float*)d_in[4];
    const float* W2    = (const float*)d_in[5];
    const float* root2 = (const float*)d_in[6];
    const float* b2    = (const float*)d_in[7];
    float* out = (float*)d_out;

    k_fused0<<<592, 256>>>(W2, root2);
    k_hist<<<(EE + 255) / 256, 256>>>(ei, et);
    k_scan<<<40, 1024>>>();
    k_perm<<<(EE + 255) / 256, 256>>>(ei, et);
    k_layer1<<<NN / 8, 256>>>(W1, root1, b1);
    cudaFuncSetAttribute(k_gemm, cudaFuncAttributeMaxDynamicSharedMemorySize, SM_TOTAL);
    k_gemm<<<dim3(NTILES, 3), 256, SM_TOTAL>>>(b2, out);
    k_layer2<<<NN / 8, 256>>>(out);
}

// round 8
// speedup vs baseline: 1.4068x; 1.0230x over previous
#include <cuda_runtime.h>
#include <cuda_fp16.h>
#include <cstdint>

#define NN 40000
#define EE 640000
#define RRL 8
#define HH 128
#define CC 64
#define NRSEG (NN*RRL)
#define NTILES 313          // ceil(40000/128)

// ---------------- scratch (__device__ globals; no allocation) ----------------
__device__ int   g_cnt2[NRSEG];
__device__ float g_inv[NRSEG];
__device__ int   g_offs[NN];
__device__ int   g_cursor[NN];
__device__ int2  g_edge[EE];            // {.x=(rel<<16)|src, .y=scale bits}, dst-grouped
__device__ int   g_bsum[40];
__device__ int   g_bflag[40];
__device__ uint32_t g_h[(size_t)NTILES * 128 * 64];   // layer-1 out, half2-packed [row][64]
__device__ __half g_w2t[9 * CC * HH];                 // W2^T / root2^T fp16 [m][c][k]
__device__ __half g_hall[(size_t)RRL * NN * CC];      // h @ W2[r] fp16, permuted row layout

// ---------------- hist (+ one-shot W2/root2 -> fp16 transpose fold) ----------------
__global__ void k_hist(const int* __restrict__ ei, const int* __restrict__ et,
                       const float* __restrict__ W2, const float* __restrict__ root2) {
    int gid = blockIdx.x * blockDim.x + threadIdx.x;
    if (gid < 9 * CC * HH) {   // 73728 one-shot conversions folded into idle BW
        int m = gid >> 13;
        int rem = gid & 8191;
        int c = rem >> 7;
        int k = rem & 127;
        float v = (m < 8) ? W2[((size_t)m * HH + k) * CC + c] : root2[(size_t)k * CC + c];
        g_w2t[gid] = __float2half_rn(v);
    }
    if (gid >= EE) return;
    int dst = ei[EE + gid];
    int rel = et[gid];
    atomicAdd(&g_cnt2[dst * RRL + rel], 1);
}

// ---------------- single-kernel scan (decoupled lookback) + inv ----------------
__global__ void k_scan() {
    __shared__ int s[1024];
    __shared__ int sprev;
    int b = blockIdx.x, tid = threadIdx.x;
    int i = b * 1024 + tid;
    int v = 0;
    if (i < NN) {
        int4 c0 = ((const int4*)g_cnt2)[i * 2];
        int4 c1 = ((const int4*)g_cnt2)[i * 2 + 1];
        v = c0.x + c0.y + c0.z + c0.w + c1.x + c1.y + c1.z + c1.w;
    }
    s[tid] = v;
    __syncthreads();
    for (int off = 1; off < 1024; off <<= 1) {
        int t = (tid >= off) ? s[tid - off] : 0;
        __syncthreads();
        s[tid] += t;
        __syncthreads();
    }
    if (tid == 1023) {
        int total = s[1023];
        int prev = 0;
        if (b > 0) {
            while (atomicAdd(&g_bflag[b - 1], 0) == 0) { }
            prev = g_bsum[b - 1];
        }
        g_bsum[b] = prev + total;
        __threadfence();
        atomicExch(&g_bflag[b], 1);
        sprev = prev;
    }
    for (int j = b * 1024 + tid; j < NRSEG; j += 40 * 1024) {
        int c = g_cnt2[j];
        g_inv[j] = 1.0f / (float)(c > 0 ? c : 1);
    }
    __syncthreads();
    if (i < NN) g_offs[i] = s[tid] - v + sprev;
}

__global__ void k_perm(const int* __restrict__ ei, const int* __restrict__ et) {
    int e = blockIdx.x * blockDim.x + threadIdx.x;
    if (e >= EE) return;
    int dst = ei[EE + e];
    int rel = et[e];
    int src = ei[e];
    int pos = g_offs[dst] + atomicAdd(&g_cursor[dst], 1);
    float s = g_inv[dst * RRL + rel];
    g_edge[pos] = make_int2((rel << 16) | src, __float_as_int(s));
}

// ---------------- layer 1: warp per dst, 8-deep MLP, writes fp16 (half2-packed) ----------------
__global__ void k_layer1(const float* __restrict__ W1, const float* __restrict__ root1,
                         const float* __restrict__ b1) {
    int w = (blockIdx.x * blockDim.x + threadIdx.x) >> 5;
    int lane = threadIdx.x & 31;
    if (w >= NN) return;
    int beg = g_offs[w];
    int end = (w == NN - 1) ? EE : g_offs[w + 1];
    int cnt = end - beg;
    float4 acc = ((const float4*)root1)[w * 32 + lane];
    float4 bb = ((const float4*)b1)[lane];
    acc.x += bb.x; acc.y += bb.y; acc.z += bb.z; acc.w += bb.w;
    const float4* W1v = (const float4*)W1;
    int i = 0;
    for (; i + 8 <= cnt; i += 8) {
        int2 e[8]; float4 v[8];
#pragma unroll
        for (int j = 0; j < 8; j++) e[j] = g_edge[beg + i + j];
#pragma unroll
        for (int j = 0; j < 8; j++)
            v[j] = W1v[(size_t)((e[j].x >> 16) * NN + (e[j].x & 0xFFFF)) * 32 + lane];
#pragma unroll
        for (int j = 0; j < 8; j++) {
            float s = __int_as_float(e[j].y);
            acc.x += v[j].x * s;
            acc.y += v[j].y * s;
            acc.z += v[j].z * s;
            acc.w += v[j].w * s;
        }
    }
    for (; i < cnt; i++) {
        int2 e = g_edge[beg + i];
        float s = __int_as_float(e.y);
        float4 v = W1v[(size_t)((e.x >> 16) * NN + (e.x & 0xFFFF)) * 32 + lane];
        acc.x += v.x * s; acc.y += v.y * s; acc.z += v.z * s; acc.w += v.w * s;
    }
    __half2 p0 = __floats2half2_rn(fmaxf(acc.x, 0.0f), fmaxf(acc.y, 0.0f));
    __half2 p1 = __floats2half2_rn(fmaxf(acc.z, 0.0f), fmaxf(acc.w, 0.0f));
    ((uint2*)g_h)[w * 32 + lane] = make_uint2(*(uint32_t*)&p0, *(uint32_t*)&p1);
}

// ---------------- GEMM via fp16 mma.sync m16n8k16: A staged once, 3 r-slices per CTA ----------------
// g_hall rows use fragment-native permuted layout: half2-slot s holds logical
// c-pair (s&7)*8 + (s>>3)*2. k_layer2 reads with the inverse map.
#define PAD2 68
#define SM_TOTAL ((128 + 64) * PAD2 * 4)   // 52224 bytes

__global__ void __launch_bounds__(256) k_gemm(const float* __restrict__ b2,
                                              float* __restrict__ out) {
    extern __shared__ uint32_t sm32[];
    uint32_t* As = sm32;                // [128][PAD2] half2 words
    uint32_t* Bs = sm32 + 128 * PAD2;   // [64][PAD2]  half2 words (B^T: [c][k])
    int t = threadIdx.x;
    int tile = blockIdx.x;
    int rbase = blockIdx.y * 3;

    // stage A once: 128 rows x 64 half2 words = 2048 uint4
    const uint4* asrc = (const uint4*)(g_h + (size_t)tile * 128 * 64);
#pragma unroll
    for (int j = 0; j < 8; j++) {
        int f = t + j * 256;           // 0..2047
        int row = f >> 4, q = f & 15;
        *(uint4*)&As[row * PAD2 + (q << 2)] = asrc[f];
    }

    int warp = t >> 5, lane = t & 31;
    int g = lane >> 2;        // groupID 0..7
    int tig = lane & 3;       // threadID_in_group
    int rA = warp * 16 + g;
    int n0 = tile * 128 + warp * 16 + g;
    int n1 = n0 + 8;

    for (int rr = 0; rr < 3; rr++) {
        int r = rbase + rr;
        __syncthreads();      // Bs overwrite safety + first-iter As visibility
        const uint4* bsrc = (const uint4*)(g_w2t + (size_t)r * CC * HH);
#pragma unroll
        for (int j = 0; j < 4; j++) {
            int f = t + j * 256;       // 0..1023
            int row = f >> 4, q = f & 15;
            *(uint4*)&Bs[row * PAD2 + (q << 2)] = bsrc[f];
        }
        __syncthreads();

        float acc[8][4];
#pragma unroll
        for (int nt = 0; nt < 8; nt++)
#pragma unroll
            for (int q = 0; q < 4; q++) acc[nt][q] = 0.0f;

#pragma unroll
        for (int ks = 0; ks < 8; ks++) {
            int j0 = ks * 8 + tig;     // half2-word index; k = 2*j0
            uint32_t a0 = As[rA * PAD2 + j0];
            uint32_t a1 = As[(rA + 8) * PAD2 + j0];
            uint32_t a2 = As[rA * PAD2 + j0 + 4];
            uint32_t a3 = As[(rA + 8) * PAD2 + j0 + 4];
#pragma unroll
            for (int nt = 0; nt < 8; nt++) {
                int brow = nt * 8 + g;
                uint32_t b0 = Bs[brow * PAD2 + j0];
                uint32_t b1_ = Bs[brow * PAD2 + j0 + 4];
                asm volatile(
                    "mma.sync.aligned.m16n8k16.row.col.f32.f16.f16.f32 "
                    "{%0,%1,%2,%3}, {%4,%5,%6,%7}, {%8,%9}, {%0,%1,%2,%3};"
                    : "+f"(acc[nt][0]), "+f"(acc[nt][1]), "+f"(acc[nt][2]), "+f"(acc[nt][3])
                    : "r"(a0), "r"(a1), "r"(a2), "r"(a3), "r"(b0), "r"(b1_));
            }
        }

        if (r < 8) {
            // permuted-layout vectorized stores: 2x uint4 per row-half per thread
            __half2* hall2 = (__half2*)g_hall;
            uint32_t p0[8], p1[8];
#pragma unroll
            for (int nt = 0; nt < 8; nt++) {
                __half2 h0 = __floats2half2_rn(acc[nt][0], acc[nt][1]);
                __half2 h1 = __floats2half2_rn(acc[nt][2], acc[nt][3]);
                p0[nt] = *(uint32_t*)&h0;
                p1[nt] = *(uint32_t*)&h1;
            }
            if (n0 < NN) {
                __half2* rb = hall2 + ((size_t)r * NN + n0) * 32 + tig * 8;
                *(uint4*)rb       = make_uint4(p0[0], p0[1], p0[2], p0[3]);
                *(uint4*)(rb + 4) = make_uint4(p0[4], p0[5], p0[6], p0[7]);
            }
            if (n1 < NN) {
                __half2* rb = hall2 + ((size_t)r * NN + n1) * 32 + tig * 8;
                *(uint4*)rb       = make_uint4(p1[0], p1[1], p1[2], p1[3]);
                *(uint4*)(rb + 4) = make_uint4(p1[4], p1[5], p1[6], p1[7]);
            }
        } else {
#pragma unroll
            for (int nt = 0; nt < 8; nt++) {
                int c = nt * 8 + tig * 2;
                float2 bb = *(const float2*)&b2[c];
                if (n0 < NN) *(float2*)&out[(size_t)n0 * CC + c] = make_float2(acc[nt][0] + bb.x, acc[nt][1] + bb.y);
                if (n1 < NN) *(float2*)&out[(size_t)n1 * CC + c] = make_float2(acc[nt][2] + bb.x, acc[nt][3] + bb.y);
            }
        }
    }
}

// ---------------- layer 2: warp per dst, gather fp16 h_all (permuted rows) ----------------
__global__ void k_layer2(float* __restrict__ out) {
    int w = (blockIdx.x * blockDim.x + threadIdx.x) >> 5;
    int lane = threadIdx.x & 31;
    if (w >= NN) return;
    int beg = g_offs[w];
    int end = (w == NN - 1) ? EE : g_offs[w + 1];
    int cnt = end - beg;
    // lane's half2-slot 'lane' holds logical c-pair cl:
    int cl = ((lane & 7) << 3) + ((lane >> 3) << 1);
    float2 acc = *(const float2*)&out[(size_t)w * CC + cl];   // h@root2 + b2 from k_gemm
    const __half2* hv = (const __half2*)g_hall;
    int i = 0;
    for (; i + 8 <= cnt; i += 8) {
        int2 e[8]; __half2 v[8];
#pragma unroll
        for (int j = 0; j < 8; j++) e[j] = g_edge[beg + i + j];
#pragma unroll
        for (int j = 0; j < 8; j++)
            v[j] = hv[(size_t)((e[j].x >> 16) * NN + (e[j].x & 0xFFFF)) * 32 + lane];
#pragma unroll
        for (int j = 0; j < 8; j++) {
            float s = __int_as_float(e[j].y);
            float2 f = __half22float2(v[j]);
            acc.x += f.x * s;
            acc.y += f.y * s;
        }
    }
    for (; i < cnt; i++) {
        int2 e = g_edge[beg + i];
        float s = __int_as_float(e.y);
        float2 f = __half22float2(hv[(size_t)((e.x >> 16) * NN + (e.x & 0xFFFF)) * 32 + lane]);
        acc.x += f.x * s; acc.y += f.y * s;
    }
    *(float2*)&out[(size_t)w * CC + cl] = acc;
}

// ---------------- launch ----------------
extern "C" void kernel_launch(void* const* d_in, const int* in_sizes, int n_in,
                              void* d_out, int out_size) {
    (void)in_sizes; (void)n_in; (void)out_size;
    const int*   ei    = (const int*)d_in[0];
    const int*   et    = (const int*)d_in[1];
    const float* W1    = (const float*)d_in[2];
    const float* root1 = (const float*)d_in[3];
    const float* b1    = (const float*)d_in[4];
    const float* W2    = (const float*)d_in[5];
    const float* root2 = (const float*)d_in[6];
    const float* b2    = (const float*)d_in[7];
    float* out = (float*)d_out;

    void *p_cnt2 = nullptr, *p_cursor = nullptr, *p_bflag = nullptr;
    cudaGetSymbolAddress(&p_cnt2, g_cnt2);
    cudaGetSymbolAddress(&p_cursor, g_cursor);
    cudaGetSymbolAddress(&p_bflag, g_bflag);
    cudaMemsetAsync(p_cnt2, 0, NRSEG * sizeof(int));
    cudaMemsetAsync(p_cursor, 0, NN * sizeof(int));
    cudaMemsetAsync(p_bflag, 0, 40 * sizeof(int));

    k_hist<<<(EE + 255) / 256, 256>>>(ei, et, W2, root2);
    k_scan<<<40, 1024>>>();
    k_perm<<<(EE + 255) / 256, 256>>>(ei, et);
    k_layer1<<<NN / 8, 256>>>(W1, root1, b1);
    cudaFuncSetAttribute(k_gemm, cudaFuncAttributeMaxDynamicSharedMemorySize, SM_TOTAL);
    k_gemm<<<dim3(NTILES, 3), 256, SM_TOTAL>>>(b2, out);
    k_layer2<<<NN / 8, 256>>>(out);
}